// round 7
// baseline (speedup 1.0000x reference)
#include <cuda_runtime.h>
#include <math.h>

// Piecewise-quadratic 1/sqrt(x).
// Segment selection: bit-trick log2 estimate (error < 0.07 segment), then one
// exact compare vs breaks[s0] (warp shuffle) reproducing
// jnp.searchsorted(breaks, x, side='left') - 1 bit-exactly.
// R7 (final): the R1/R3 twice-proven optimum — .cs streaming loads+stores,
// grid 4736 x 256, 32 regs, occupancy-driven MLP, single launch with
// per-thread constant derivation. Measured 160.5us kernel / 80.5% DRAM
// (the structural read+write streaming wall on GB300) in two prior rounds;
// all tested perturbations (ILP batching, cache-policy variants, exact-fit
// grids) were neutral or worse.

__device__ __forceinline__ float pw_eval(float x, float K1, float K2,
                                         float brk, float ca, float cb, float cc,
                                         int segmax) {
    // t ~= K*log2(x/LO) + 0.5, bit-trick error in [-0.066, +0.066]
    float tf = (float)__float_as_int(x);
    float t  = fmaf(tf, K1, K2);
    int s0 = (int)t;                          // true seg is s0-1 or s0
    float bmid = __shfl_sync(0xffffffffu, brk, s0);
    int s = s0 - 1 + (x > bmid ? 1 : 0);      // strict '>' == searchsorted left
    s = max(s, 0);
    s = min(s, segmax);
    float a = __shfl_sync(0xffffffffu, ca, s);
    float b = __shfl_sync(0xffffffffu, cb, s);
    float c = __shfl_sync(0xffffffffu, cc, s);
    return fmaf(fmaf(a, x, b), x, c);
}

__device__ __forceinline__ float4 pw_eval4(float4 v, float K1, float K2,
                                           float brk, float ca, float cb, float cc,
                                           int segmax) {
    float4 r;
    r.x = pw_eval(v.x, K1, K2, brk, ca, cb, cc, segmax);
    r.y = pw_eval(v.y, K1, K2, brk, ca, cb, cc, segmax);
    r.z = pw_eval(v.z, K1, K2, brk, ca, cb, cc, segmax);
    r.w = pw_eval(v.w, K1, K2, brk, ca, cb, cc, segmax);
    return r;
}

__global__ void __launch_bounds__(256)
pw_main_kernel(const float* __restrict__ x,
               const float* __restrict__ breaks,
               const float* __restrict__ coeffs,
               float* __restrict__ y,
               int n, int nseg) {
    const int lane = threadIdx.x & 31;

    // Per-warp register tables: breaks in lanes 0..nseg, coeffs in lanes 0..nseg-1
    float brk = __int_as_float(0x7f800000);   // +inf in unused lanes
    if (lane <= nseg) brk = __ldg(breaks + lane);
    float ca = 0.0f, cb = 0.0f, cc = 0.0f;
    if (lane < nseg) {
        ca = __ldg(coeffs + 3 * lane + 0);
        cb = __ldg(coeffs + 3 * lane + 1);
        cc = __ldg(coeffs + 3 * lane + 2);
    }

    // Derive bit-trick constants from the actual breaks (once per thread;
    // 2 MUFUs amortized over ~28 iterations -> negligible).
    const float lo = __ldg(breaks);
    const float hi = __ldg(breaks + nseg);
    const float l2lo = __log2f(lo);
    const float K  = (float)nseg / (__log2f(hi) - l2lo);
    const float K1 = K * (1.0f / 8388608.0f);                       // K * 2^-23
    const float K2 = fmaf(K, (0.04303565f - 127.0f) - l2lo, 0.5f);  // centered
    const int segmax = nseg - 1;

    const int n4 = n >> 2;
    const float4* __restrict__ x4 = (const float4*)x;
    float4*       __restrict__ y4 = (float4*)y;

    const int T   = gridDim.x * blockDim.x;
    const int tid = blockIdx.x * blockDim.x + threadIdx.x;

    // Full chunks: every lane of the warp is in range -> no guards at all.
    int i = tid;
    for (; (i - lane) + 32 <= n4; i += T) {
        float4 v = __ldcs(x4 + i);
        float4 r = pw_eval4(v, K1, K2, brk, ca, cb, cc, segmax);
        __stcs(y4 + i, r);
    }
    // One partial warp chunk at most: guarded store, full-warp shuffles.
    if ((i - lane) < n4) {
        int j = (i < n4) ? i : (n4 - 1);
        float4 v = __ldcs(x4 + j);
        float4 r = pw_eval4(v, K1, K2, brk, ca, cb, cc, segmax);
        if (i < n4) __stcs(y4 + j, r);
    }
    // Scalar tail (n % 4 != 0), same warp-safe pattern.
    const int base = n4 << 2;
    for (int k = base + tid; (k - lane) < n; k += T) {
        int j = (k < n) ? k : (n - 1);
        float v = __ldg(x + j);
        float r = pw_eval(v, K1, K2, brk, ca, cb, cc, segmax);
        if (k < n) y[j] = r;
    }
}

extern "C" void kernel_launch(void* const* d_in, const int* in_sizes, int n_in,
                              void* d_out, int out_size) {
    const float* x      = (const float*)d_in[0];
    const float* breaks = (const float*)d_in[1];
    const float* coeffs = (const float*)d_in[2];
    float*       y      = (float*)d_out;

    const int n    = in_sizes[0];
    const int nseg = in_sizes[2] / 3;   // coeffs is [nseg, 3]

    const int n4 = n >> 2;
    const int work = (n4 > 0) ? n4 : n;
    int blocks = (work + 255) / 256;
    if (blocks > 4736) blocks = 4736;   // R1/R3-proven optimum
    if (blocks < 1)    blocks = 1;
    pw_main_kernel<<<blocks, 256>>>(x, breaks, coeffs, y, n, nseg);
}

// round 8
// speedup vs baseline: 1.1498x; 1.1498x over previous
#include <cuda_runtime.h>
#include <math.h>

// Piecewise-quadratic 1/sqrt(x).
// Segment selection: bit-trick log2 estimate (error < 0.07 segment), then one
// exact compare vs breaks[s0] (warp shuffle) reproducing
// jnp.searchsorted(breaks, x, side='left') - 1 bit-exactly.
// R8: the R1/R3 twice-proven optimum (.cs loads+stores, grid 4736 x 256,
// 32 regs, occupancy-driven MLP, single launch). R7 ran this exact binary
// and regressed 18% with issue% +40% at identical instruction counts ->
// clock-droop artifact, not code. Hot loop unchanged.

__device__ __forceinline__ float pw_eval(float x, float K1, float K2,
                                         float brk, float ca, float cb, float cc,
                                         int segmax) {
    // t ~= K*log2(x/LO) + 0.5, bit-trick error in [-0.066, +0.066]
    float tf = (float)__float_as_int(x);
    float t  = fmaf(tf, K1, K2);
    int s0 = (int)t;                          // true seg is s0-1 or s0
    float bmid = __shfl_sync(0xffffffffu, brk, s0);
    int s = s0 - 1 + (x > bmid ? 1 : 0);      // strict '>' == searchsorted left
    s = max(s, 0);                            // reference's clip (x == LO case)
    s = min(s, segmax);
    float a = __shfl_sync(0xffffffffu, ca, s);
    float b = __shfl_sync(0xffffffffu, cb, s);
    float c = __shfl_sync(0xffffffffu, cc, s);
    return fmaf(fmaf(a, x, b), x, c);
}

__device__ __forceinline__ float4 pw_eval4(float4 v, float K1, float K2,
                                           float brk, float ca, float cb, float cc,
                                           int segmax) {
    float4 r;
    r.x = pw_eval(v.x, K1, K2, brk, ca, cb, cc, segmax);
    r.y = pw_eval(v.y, K1, K2, brk, ca, cb, cc, segmax);
    r.z = pw_eval(v.z, K1, K2, brk, ca, cb, cc, segmax);
    r.w = pw_eval(v.w, K1, K2, brk, ca, cb, cc, segmax);
    return r;
}

__global__ void __launch_bounds__(256)
pw_main_kernel(const float* __restrict__ x,
               const float* __restrict__ breaks,
               const float* __restrict__ coeffs,
               float* __restrict__ y,
               int n, int nseg) {
    const int lane = threadIdx.x & 31;

    // Per-warp register tables: breaks in lanes 0..nseg, coeffs in lanes 0..nseg-1
    float brk = __int_as_float(0x7f800000);   // +inf in unused lanes
    if (lane <= nseg) brk = __ldg(breaks + lane);
    float ca = 0.0f, cb = 0.0f, cc = 0.0f;
    if (lane < nseg) {
        ca = __ldg(coeffs + 3 * lane + 0);
        cb = __ldg(coeffs + 3 * lane + 1);
        cc = __ldg(coeffs + 3 * lane + 2);
    }

    // Derive bit-trick constants from the actual breaks (once per thread;
    // 2 MUFUs amortized over ~28 iterations -> negligible).
    const float lo = __ldg(breaks);
    const float hi = __ldg(breaks + nseg);
    const float l2lo = __log2f(lo);
    const float K  = (float)nseg / (__log2f(hi) - l2lo);
    const float K1 = K * (1.0f / 8388608.0f);                       // K * 2^-23
    const float K2 = fmaf(K, (0.04303565f - 127.0f) - l2lo, 0.5f);  // centered
    const int segmax = nseg - 1;

    const int n4 = n >> 2;
    const float4* __restrict__ x4 = (const float4*)x;
    float4*       __restrict__ y4 = (float4*)y;

    const int T   = gridDim.x * blockDim.x;
    const int tid = blockIdx.x * blockDim.x + threadIdx.x;

    // Hot loop: every lane of the warp in range -> no guards at all.
    int i = tid;
    for (; (i - lane) + 32 <= n4; i += T) {
        float4 v = __ldcs(x4 + i);
        float4 r = pw_eval4(v, K1, K2, brk, ca, cb, cc, segmax);
        __stcs(y4 + i, r);
    }
    // One partial warp chunk at most: guarded store, full-warp shuffles.
    if ((i - lane) < n4) {
        int j = min(i, n4 - 1);
        float4 v = __ldcs(x4 + j);
        float4 r = pw_eval4(v, K1, K2, brk, ca, cb, cc, segmax);
        if (i < n4) __stcs(y4 + j, r);
    }
    // Scalar tail (n % 4 != 0), same warp-safe pattern.
    const int base = n4 << 2;
    for (int k = base + tid; (k - lane) < n; k += T) {
        int j = min(k, n - 1);
        float v = __ldg(x + j);
        float r = pw_eval(v, K1, K2, brk, ca, cb, cc, segmax);
        if (k < n) y[j] = r;
    }
}

extern "C" void kernel_launch(void* const* d_in, const int* in_sizes, int n_in,
                              void* d_out, int out_size) {
    const float* x      = (const float*)d_in[0];
    const float* breaks = (const float*)d_in[1];
    const float* coeffs = (const float*)d_in[2];
    float*       y      = (float*)d_out;

    const int n    = in_sizes[0];
    const int nseg = in_sizes[2] / 3;   // coeffs is [nseg, 3]

    const int n4 = n >> 2;
    const int work = (n4 > 0) ? n4 : n;
    int blocks = (work + 255) / 256;
    if (blocks > 4736) blocks = 4736;   // R1/R3-proven optimum
    if (blocks < 1)    blocks = 1;
    pw_main_kernel<<<blocks, 256>>>(x, breaks, coeffs, y, n, nseg);
}

// round 9
// speedup vs baseline: 1.1525x; 1.0024x over previous
#include <cuda_runtime.h>
#include <math.h>

// Piecewise-quadratic 1/sqrt(x).
// Segment selection: bit-trick log2 estimate (error < 0.07 segment), then one
// exact compare vs breaks[s0] (warp shuffle) reproducing
// jnp.searchsorted(breaks, x, side='left') - 1 bit-exactly.
// R9: proven hot loop (.cs/.cs, 32 regs, occupancy-driven MLP, single launch)
// with 128-thread CTAs at grid 9472 (same total warps as the 4-times-measured
// 4736x256 optimum) to test whether finer CTA-completion granularity trims
// the tail-wave imbalance. All else identical to R8.

__device__ __forceinline__ float pw_eval(float x, float K1, float K2,
                                         float brk, float ca, float cb, float cc,
                                         int segmax) {
    // t ~= K*log2(x/LO) + 0.5, bit-trick error in [-0.066, +0.066]
    float tf = (float)__float_as_int(x);
    float t  = fmaf(tf, K1, K2);
    int s0 = (int)t;                          // true seg is s0-1 or s0
    float bmid = __shfl_sync(0xffffffffu, brk, s0);
    int s = s0 - 1 + (x > bmid ? 1 : 0);      // strict '>' == searchsorted left
    s = max(s, 0);                            // reference's clip (x == LO case)
    s = min(s, segmax);
    float a = __shfl_sync(0xffffffffu, ca, s);
    float b = __shfl_sync(0xffffffffu, cb, s);
    float c = __shfl_sync(0xffffffffu, cc, s);
    return fmaf(fmaf(a, x, b), x, c);
}

__device__ __forceinline__ float4 pw_eval4(float4 v, float K1, float K2,
                                           float brk, float ca, float cb, float cc,
                                           int segmax) {
    float4 r;
    r.x = pw_eval(v.x, K1, K2, brk, ca, cb, cc, segmax);
    r.y = pw_eval(v.y, K1, K2, brk, ca, cb, cc, segmax);
    r.z = pw_eval(v.z, K1, K2, brk, ca, cb, cc, segmax);
    r.w = pw_eval(v.w, K1, K2, brk, ca, cb, cc, segmax);
    return r;
}

__global__ void __launch_bounds__(128)
pw_main_kernel(const float* __restrict__ x,
               const float* __restrict__ breaks,
               const float* __restrict__ coeffs,
               float* __restrict__ y,
               int n, int nseg) {
    const int lane = threadIdx.x & 31;

    // Per-warp register tables: breaks in lanes 0..nseg, coeffs in lanes 0..nseg-1
    float brk = __int_as_float(0x7f800000);   // +inf in unused lanes
    if (lane <= nseg) brk = __ldg(breaks + lane);
    float ca = 0.0f, cb = 0.0f, cc = 0.0f;
    if (lane < nseg) {
        ca = __ldg(coeffs + 3 * lane + 0);
        cb = __ldg(coeffs + 3 * lane + 1);
        cc = __ldg(coeffs + 3 * lane + 2);
    }

    // Derive bit-trick constants from the actual breaks (once per thread;
    // 2 MUFUs amortized over ~28 iterations -> negligible).
    const float lo = __ldg(breaks);
    const float hi = __ldg(breaks + nseg);
    const float l2lo = __log2f(lo);
    const float K  = (float)nseg / (__log2f(hi) - l2lo);
    const float K1 = K * (1.0f / 8388608.0f);                       // K * 2^-23
    const float K2 = fmaf(K, (0.04303565f - 127.0f) - l2lo, 0.5f);  // centered
    const int segmax = nseg - 1;

    const int n4 = n >> 2;
    const float4* __restrict__ x4 = (const float4*)x;
    float4*       __restrict__ y4 = (float4*)y;

    const int T   = gridDim.x * blockDim.x;
    const int tid = blockIdx.x * blockDim.x + threadIdx.x;

    // Hot loop: every lane of the warp in range -> no guards at all.
    int i = tid;
    for (; (i - lane) + 32 <= n4; i += T) {
        float4 v = __ldcs(x4 + i);
        float4 r = pw_eval4(v, K1, K2, brk, ca, cb, cc, segmax);
        __stcs(y4 + i, r);
    }
    // One partial warp chunk at most: guarded store, full-warp shuffles.
    if ((i - lane) < n4) {
        int j = min(i, n4 - 1);
        float4 v = __ldcs(x4 + j);
        float4 r = pw_eval4(v, K1, K2, brk, ca, cb, cc, segmax);
        if (i < n4) __stcs(y4 + j, r);
    }
    // Scalar tail (n % 4 != 0), same warp-safe pattern.
    const int base = n4 << 2;
    for (int k = base + tid; (k - lane) < n; k += T) {
        int j = min(k, n - 1);
        float v = __ldg(x + j);
        float r = pw_eval(v, K1, K2, brk, ca, cb, cc, segmax);
        if (k < n) y[j] = r;
    }
}

extern "C" void kernel_launch(void* const* d_in, const int* in_sizes, int n_in,
                              void* d_out, int out_size) {
    const float* x      = (const float*)d_in[0];
    const float* breaks = (const float*)d_in[1];
    const float* coeffs = (const float*)d_in[2];
    float*       y      = (float*)d_out;

    const int n    = in_sizes[0];
    const int nseg = in_sizes[2] / 3;   // coeffs is [nseg, 3]

    const int THREADS = 128;
    const int n4 = n >> 2;
    const int work = (n4 > 0) ? n4 : n;
    int blocks = (work + THREADS - 1) / THREADS;
    if (blocks > 9472) blocks = 9472;   // same total warps as 4736 x 256
    if (blocks < 1)    blocks = 1;
    pw_main_kernel<<<blocks, THREADS>>>(x, breaks, coeffs, y, n, nseg);
}

// round 10
// speedup vs baseline: 1.1561x; 1.0031x over previous
#include <cuda_runtime.h>
#include <math.h>

// Piecewise-quadratic 1/sqrt(x) — FINAL converged form.
//
// Segment selection: bit-trick log2 estimate (error < 0.07 segment), then one
// exact compare vs breaks[s0] (warp shuffle) reproducing
// jnp.searchsorted(breaks, x, side='left') - 1 bit-exactly. Coefficients live
// in per-warp registers, fetched via 3 shuffles; zero per-element table loads.
//
// Operating point (reproduced 5x across R1/R3/R4/R8/R9): 160.5-160.6us kernel,
// 6.38 TB/s (80% of 8TB/s spec — the measured mixed read+write streaming wall
// on GB300), occ ~94%, 32 regs, issue 38% (2.6x compute headroom).
// All tested perturbations were neutral or worse:
//   - ILP load batching (R2): -occupancy, +regs -> 177us
//   - default / .lu cache policies (R4/R5): DRAM% unchanged
//   - exact-fit grid 4096 (R6): -occupancy -> 165us
//   - 256-thread vs 128-thread CTAs (R8/R9): identical
// R7 (same binary, 189us) demonstrated session clock droop; discounted.

__device__ __forceinline__ float pw_eval(float x, float K1, float K2,
                                         float brk, float ca, float cb, float cc,
                                         int segmax) {
    // t ~= K*log2(x/LO) + 0.5, bit-trick error in [-0.066, +0.066]
    float tf = (float)__float_as_int(x);
    float t  = fmaf(tf, K1, K2);
    int s0 = (int)t;                          // true seg is s0-1 or s0
    float bmid = __shfl_sync(0xffffffffu, brk, s0);
    int s = s0 - 1 + (x > bmid ? 1 : 0);      // strict '>' == searchsorted left
    s = max(s, 0);                            // reference's clip (x == LO case)
    s = min(s, segmax);
    float a = __shfl_sync(0xffffffffu, ca, s);
    float b = __shfl_sync(0xffffffffu, cb, s);
    float c = __shfl_sync(0xffffffffu, cc, s);
    return fmaf(fmaf(a, x, b), x, c);
}

__device__ __forceinline__ float4 pw_eval4(float4 v, float K1, float K2,
                                           float brk, float ca, float cb, float cc,
                                           int segmax) {
    float4 r;
    r.x = pw_eval(v.x, K1, K2, brk, ca, cb, cc, segmax);
    r.y = pw_eval(v.y, K1, K2, brk, ca, cb, cc, segmax);
    r.z = pw_eval(v.z, K1, K2, brk, ca, cb, cc, segmax);
    r.w = pw_eval(v.w, K1, K2, brk, ca, cb, cc, segmax);
    return r;
}

__global__ void __launch_bounds__(128)
pw_main_kernel(const float* __restrict__ x,
               const float* __restrict__ breaks,
               const float* __restrict__ coeffs,
               float* __restrict__ y,
               int n, int nseg) {
    const int lane = threadIdx.x & 31;

    // Per-warp register tables: breaks in lanes 0..nseg, coeffs in lanes 0..nseg-1
    float brk = __int_as_float(0x7f800000);   // +inf in unused lanes
    if (lane <= nseg) brk = __ldg(breaks + lane);
    float ca = 0.0f, cb = 0.0f, cc = 0.0f;
    if (lane < nseg) {
        ca = __ldg(coeffs + 3 * lane + 0);
        cb = __ldg(coeffs + 3 * lane + 1);
        cc = __ldg(coeffs + 3 * lane + 2);
    }

    // Derive bit-trick constants from the actual breaks (once per thread;
    // 2 MUFUs amortized over ~28 iterations -> negligible).
    const float lo = __ldg(breaks);
    const float hi = __ldg(breaks + nseg);
    const float l2lo = __log2f(lo);
    const float K  = (float)nseg / (__log2f(hi) - l2lo);
    const float K1 = K * (1.0f / 8388608.0f);                       // K * 2^-23
    const float K2 = fmaf(K, (0.04303565f - 127.0f) - l2lo, 0.5f);  // centered
    const int segmax = nseg - 1;

    const int n4 = n >> 2;
    const float4* __restrict__ x4 = (const float4*)x;
    float4*       __restrict__ y4 = (float4*)y;

    const int T   = gridDim.x * blockDim.x;
    const int tid = blockIdx.x * blockDim.x + threadIdx.x;

    // Hot loop: every lane of the warp in range -> no guards at all.
    int i = tid;
    for (; (i - lane) + 32 <= n4; i += T) {
        float4 v = __ldcs(x4 + i);
        float4 r = pw_eval4(v, K1, K2, brk, ca, cb, cc, segmax);
        __stcs(y4 + i, r);
    }
    // One partial warp chunk at most: guarded store, full-warp shuffles.
    if ((i - lane) < n4) {
        int j = min(i, n4 - 1);
        float4 v = __ldcs(x4 + j);
        float4 r = pw_eval4(v, K1, K2, brk, ca, cb, cc, segmax);
        if (i < n4) __stcs(y4 + j, r);
    }
    // Scalar tail (n % 4 != 0), same warp-safe pattern.
    const int base = n4 << 2;
    for (int k = base + tid; (k - lane) < n; k += T) {
        int j = min(k, n - 1);
        float v = __ldg(x + j);
        float r = pw_eval(v, K1, K2, brk, ca, cb, cc, segmax);
        if (k < n) y[j] = r;
    }
}

extern "C" void kernel_launch(void* const* d_in, const int* in_sizes, int n_in,
                              void* d_out, int out_size) {
    const float* x      = (const float*)d_in[0];
    const float* breaks = (const float*)d_in[1];
    const float* coeffs = (const float*)d_in[2];
    float*       y      = (float*)d_out;

    const int n    = in_sizes[0];
    const int nseg = in_sizes[2] / 3;   // coeffs is [nseg, 3]

    const int THREADS = 128;
    const int n4 = n >> 2;
    const int work = (n4 > 0) ? n4 : n;
    int blocks = (work + THREADS - 1) / THREADS;
    if (blocks > 9472) blocks = 9472;   // proven optimum (== 4736 x 256 warps)
    if (blocks < 1)    blocks = 1;
    pw_main_kernel<<<blocks, THREADS>>>(x, breaks, coeffs, y, n, nseg);
}

// round 11
// speedup vs baseline: 1.1582x; 1.0018x over previous
#include <cuda_runtime.h>
#include <math.h>

// Piecewise-quadratic 1/sqrt(x) — FINAL converged form (unchanged from R10,
// the session-best sample: 159.8us kernel / 6.41 TB/s / 162.56us total).
//
// Segment selection: bit-trick log2 estimate (error < 0.07 segment), then one
// exact compare vs breaks[s0] (warp shuffle) reproducing
// jnp.searchsorted(breaks, x, side='left') - 1 bit-exactly. Coefficients live
// in per-warp registers, fetched via 3 shuffles; zero per-element table loads.
//
// Operating point (reproduced 6x across R1/R3/R4/R8/R9/R10): 159.8-160.6us
// kernel, ~6.4 TB/s (80% of 8TB/s spec — the measured mixed read+write
// streaming wall on GB300), occ ~94%, 32 regs, issue 38% (2.6x compute
// headroom). All tested perturbations were neutral or worse:
//   - ILP load batching (R2): -occupancy, +regs -> 177us
//   - default / .lu cache policies (R4/R5): DRAM% unchanged
//   - exact-fit grid 4096 (R6): -occupancy -> 165us
//   - 256-thread vs 128-thread CTAs (R8/R9): identical
// R7 (same binary, 189us) demonstrated session clock droop; discounted.

__device__ __forceinline__ float pw_eval(float x, float K1, float K2,
                                         float brk, float ca, float cb, float cc,
                                         int segmax) {
    // t ~= K*log2(x/LO) + 0.5, bit-trick error in [-0.066, +0.066]
    float tf = (float)__float_as_int(x);
    float t  = fmaf(tf, K1, K2);
    int s0 = (int)t;                          // true seg is s0-1 or s0
    float bmid = __shfl_sync(0xffffffffu, brk, s0);
    int s = s0 - 1 + (x > bmid ? 1 : 0);      // strict '>' == searchsorted left
    s = max(s, 0);                            // reference's clip (x == LO case)
    s = min(s, segmax);
    float a = __shfl_sync(0xffffffffu, ca, s);
    float b = __shfl_sync(0xffffffffu, cb, s);
    float c = __shfl_sync(0xffffffffu, cc, s);
    return fmaf(fmaf(a, x, b), x, c);
}

__device__ __forceinline__ float4 pw_eval4(float4 v, float K1, float K2,
                                           float brk, float ca, float cb, float cc,
                                           int segmax) {
    float4 r;
    r.x = pw_eval(v.x, K1, K2, brk, ca, cb, cc, segmax);
    r.y = pw_eval(v.y, K1, K2, brk, ca, cb, cc, segmax);
    r.z = pw_eval(v.z, K1, K2, brk, ca, cb, cc, segmax);
    r.w = pw_eval(v.w, K1, K2, brk, ca, cb, cc, segmax);
    return r;
}

__global__ void __launch_bounds__(128)
pw_main_kernel(const float* __restrict__ x,
               const float* __restrict__ breaks,
               const float* __restrict__ coeffs,
               float* __restrict__ y,
               int n, int nseg) {
    const int lane = threadIdx.x & 31;

    // Per-warp register tables: breaks in lanes 0..nseg, coeffs in lanes 0..nseg-1
    float brk = __int_as_float(0x7f800000);   // +inf in unused lanes
    if (lane <= nseg) brk = __ldg(breaks + lane);
    float ca = 0.0f, cb = 0.0f, cc = 0.0f;
    if (lane < nseg) {
        ca = __ldg(coeffs + 3 * lane + 0);
        cb = __ldg(coeffs + 3 * lane + 1);
        cc = __ldg(coeffs + 3 * lane + 2);
    }

    // Derive bit-trick constants from the actual breaks (once per thread;
    // 2 MUFUs amortized over ~28 iterations -> negligible).
    const float lo = __ldg(breaks);
    const float hi = __ldg(breaks + nseg);
    const float l2lo = __log2f(lo);
    const float K  = (float)nseg / (__log2f(hi) - l2lo);
    const float K1 = K * (1.0f / 8388608.0f);                       // K * 2^-23
    const float K2 = fmaf(K, (0.04303565f - 127.0f) - l2lo, 0.5f);  // centered
    const int segmax = nseg - 1;

    const int n4 = n >> 2;
    const float4* __restrict__ x4 = (const float4*)x;
    float4*       __restrict__ y4 = (float4*)y;

    const int T   = gridDim.x * blockDim.x;
    const int tid = blockIdx.x * blockDim.x + threadIdx.x;

    // Hot loop: every lane of the warp in range -> no guards at all.
    int i = tid;
    for (; (i - lane) + 32 <= n4; i += T) {
        float4 v = __ldcs(x4 + i);
        float4 r = pw_eval4(v, K1, K2, brk, ca, cb, cc, segmax);
        __stcs(y4 + i, r);
    }
    // One partial warp chunk at most: guarded store, full-warp shuffles.
    if ((i - lane) < n4) {
        int j = min(i, n4 - 1);
        float4 v = __ldcs(x4 + j);
        float4 r = pw_eval4(v, K1, K2, brk, ca, cb, cc, segmax);
        if (i < n4) __stcs(y4 + j, r);
    }
    // Scalar tail (n % 4 != 0), same warp-safe pattern.
    const int base = n4 << 2;
    for (int k = base + tid; (k - lane) < n; k += T) {
        int j = min(k, n - 1);
        float v = __ldg(x + j);
        float r = pw_eval(v, K1, K2, brk, ca, cb, cc, segmax);
        if (k < n) y[j] = r;
    }
}

extern "C" void kernel_launch(void* const* d_in, const int* in_sizes, int n_in,
                              void* d_out, int out_size) {
    const float* x      = (const float*)d_in[0];
    const float* breaks = (const float*)d_in[1];
    const float* coeffs = (const float*)d_in[2];
    float*       y      = (float*)d_out;

    const int n    = in_sizes[0];
    const int nseg = in_sizes[2] / 3;   // coeffs is [nseg, 3]

    const int THREADS = 128;
    const int n4 = n >> 2;
    const int work = (n4 > 0) ? n4 : n;
    int blocks = (work + THREADS - 1) / THREADS;
    if (blocks > 9472) blocks = 9472;   // proven optimum (== 4736 x 256 warps)
    if (blocks < 1)    blocks = 1;
    pw_main_kernel<<<blocks, THREADS>>>(x, breaks, coeffs, y, n, nseg);
}